// round 2
// baseline (speedup 1.0000x reference)
#include <cuda_runtime.h>
#include <math.h>

#define DD 128
#define HH 128
#define WW 128
#define HW (HH*WW)
#define NVOX (DD*HH*WW)
#define RAD 15
#define TAPS 31

// Scratch: pass1 out (8 labels x 3 h-orders), pass2 out (8 labels x 6 (d,h)-combos)
__device__ float g_s1[(size_t)24 * NVOX];   // ~201 MB
__device__ float g_s2[(size_t)48 * NVOX];   // ~402 MB
__device__ float g_w0[TAPS];

// ---------------- f32x2 packed helpers ----------------
typedef unsigned long long u64;

__device__ __forceinline__ u64 pk2(float lo, float hi) {
    u64 r; asm("mov.b64 %0, {%1, %2};" : "=l"(r) : "f"(lo), "f"(hi)); return r;
}
__device__ __forceinline__ void upk2(float& lo, float& hi, u64 v) {
    asm("mov.b64 {%0, %1}, %2;" : "=f"(lo), "=f"(hi) : "l"(v));
}
__device__ __forceinline__ u64 ffma2(u64 a, u64 b, u64 c) {
    u64 r; asm("fma.rn.f32x2 %0, %1, %2, %3;" : "=l"(r) : "l"(a), "l"(b), "l"(c)); return r;
}

// ---------------------------------------------------------------------------
// Weight init: truncated normalized gaussian, sigma=5, radius 15.
// k1, k2 are derived on the fly as k0*d, k0*d^2.
// ---------------------------------------------------------------------------
__global__ void init_weights_kernel() {
    int t = threadIdx.x;
    if (t >= TAPS) return;
    double s = 0.0;
    for (int i = 0; i < TAPS; ++i) {
        double dd = (double)(i - RAD) / 5.0;
        s += exp(-0.5 * dd * dd);
    }
    double d = (double)(t - RAD);
    g_w0[t] = (float)(exp(-0.5 * (d / 5.0) * (d / 5.0)) / s);
}

// ---------------------------------------------------------------------------
// Pass 1: blur along H. One-hot trick: per tap, add (k0,k1,k2) to the matched
// label's smem accumulator column (dynamically indexed). Rows 24..26 = dummy
// sink for label 0. Each thread owns its own w-column: no syncs for the acc.
// ---------------------------------------------------------------------------
__global__ __launch_bounds__(128) void pass1_kernel(const int* __restrict__ seg) {
    __shared__ float acc[27 * 128];
    __shared__ float sw0[TAPS];
    int w = threadIdx.x;
    int h = blockIdx.x;
    int d = blockIdx.y;
    if (w < TAPS) sw0[w] = g_w0[w];
#pragma unroll
    for (int i = 0; i < 27; ++i) acc[i * 128 + w] = 0.0f;
    __syncthreads();   // for sw0 only

    int lo = h - RAD; if (lo < 0) lo = 0;
    int hi = h + RAD; if (hi > HH - 1) hi = HH - 1;
    const int* p = seg + (size_t)d * HW + w;
    for (int hh = lo; hh <= hi; ++hh) {
        int s = __ldg(p + (size_t)hh * WW);
        int t = hh - h + RAD;
        float k0 = sw0[t];
        float dd = (float)(hh - h);
        float k1 = k0 * dd;
        float k2 = k1 * dd;
        int off = (s == 0) ? (24 * 128 + w) : ((s - 1) * 3 * 128 + w);
        acc[off]       += k0;
        acc[off + 128] += k1;
        acc[off + 256] += k2;
    }
    size_t idx = (size_t)d * HW + (size_t)h * WW + w;
#pragma unroll
    for (int c = 0; c < 24; ++c)
        g_s1[(size_t)c * NVOX + idx] = acc[c * 128 + w];
}

// ---------------------------------------------------------------------------
// Pass 2: blur along D, f32x2 packed (each thread handles a w-pair).
// Tile: 32 d x 64 w. 256 threads = 8 d-groups x 32 w-pairs, 4 d-outputs each
// via a sliding 4-deep packed register window.
// Combos: 0:(d0,h0) 1:(d1,h0) 2:(d2,h0) 3:(d0,h1) 4:(d1,h1) 5:(d0,h2)
// ---------------------------------------------------------------------------
#define P2_DR 32
#define P2_PP (P2_DR + 2*RAD)   // 62

__global__ __launch_bounds__(256) void pass2_kernel() {
    __shared__ __align__(16) float sb[3][P2_PP][64];   // 47616 B
    __shared__ float sw0[TAPS];
    int tid   = threadIdx.x;
    int wbase = blockIdx.x * 64;
    int h     = blockIdx.y;
    int dbase = blockIdx.z * P2_DR;
    if (tid < TAPS) sw0[tid] = g_w0[tid];
    int wi   = tid & 31;
    int grp  = tid >> 5;
    int dloc = grp * 4;

    for (int l = 0; l < 8; ++l) {
        __syncthreads();
        for (int c = 0; c < 3; ++c) {
            const float* src = g_s1 + (size_t)(l * 3 + c) * NVOX + (size_t)h * WW + wbase;
            for (int i = tid; i < P2_PP * 64; i += 256) {
                int pp = i >> 6, ww = i & 63;
                int dd = dbase + pp - RAD;
                float v = 0.0f;
                if (dd >= 0 && dd < DD) v = src[(size_t)dd * HW + ww];
                sb[c][pp][ww] = v;
            }
        }
        __syncthreads();

        u64 acc[4][6];
#pragma unroll
        for (int o = 0; o < 4; ++o)
#pragma unroll
            for (int cc = 0; cc < 6; ++cc) acc[o][cc] = 0ull;

        u64 v0[4], v1[4], v2[4];
#pragma unroll
        for (int o = 0; o < 4; ++o) {
            v0[o] = *(const u64*)&sb[0][dloc + o][2 * wi];
            v1[o] = *(const u64*)&sb[1][dloc + o][2 * wi];
            v2[o] = *(const u64*)&sb[2][dloc + o][2 * wi];
        }
#pragma unroll
        for (int t = 0; t < TAPS; ++t) {
            float k0 = sw0[t];
            float dd = (float)(t - RAD);
            float k1 = k0 * dd;
            float k2 = k1 * dd;
            u64 K0 = pk2(k0, k0), K1 = pk2(k1, k1), K2 = pk2(k2, k2);
#pragma unroll
            for (int o = 0; o < 4; ++o) {
                acc[o][0] = ffma2(K0, v0[o], acc[o][0]);
                acc[o][1] = ffma2(K1, v0[o], acc[o][1]);
                acc[o][2] = ffma2(K2, v0[o], acc[o][2]);
                acc[o][3] = ffma2(K0, v1[o], acc[o][3]);
                acc[o][4] = ffma2(K1, v1[o], acc[o][4]);
                acc[o][5] = ffma2(K0, v2[o], acc[o][5]);
            }
            if (t < TAPS - 1) {
#pragma unroll
                for (int o = 0; o < 3; ++o) { v0[o] = v0[o+1]; v1[o] = v1[o+1]; v2[o] = v2[o+1]; }
                v0[3] = *(const u64*)&sb[0][dloc + t + 4][2 * wi];
                v1[3] = *(const u64*)&sb[1][dloc + t + 4][2 * wi];
                v2[3] = *(const u64*)&sb[2][dloc + t + 4][2 * wi];
            }
        }
        size_t obase = (size_t)(dbase + dloc) * HW + (size_t)h * WW + wbase + 2 * wi;
#pragma unroll
        for (int o = 0; o < 4; ++o)
#pragma unroll
            for (int cc = 0; cc < 6; ++cc)
                *(u64*)&g_s2[(size_t)(l * 6 + cc) * NVOX + obase + (size_t)o * HW] = acc[o][cc];
    }
}

// ---------------------------------------------------------------------------
// Pass 3: blur along W + descriptor assembly, own-label only.
// Voxel-major smem sm[pos][50]: the 6 own-label channels are contiguous ->
// 3x LDS.64 per tap; 10 accumulators pair into 6 packed FMAs per tap.
// ---------------------------------------------------------------------------
__global__ __launch_bounds__(128) void pass3_kernel(const int* __restrict__ seg,
                                                    float* __restrict__ out) {
    __shared__ __align__(16) float sm[WW][50];   // 25.6 KB, pad 50 kills conflicts
    __shared__ float sw0[TAPS];
    int w = threadIdx.x;
    int h = blockIdx.x;
    int d = blockIdx.y;
    if (w < TAPS) sw0[w] = g_w0[w];
    size_t base = (size_t)d * HW + (size_t)h * WW;
    for (int i = w; i < 48 * WW; i += 128) {
        int ch = i >> 7, ww = i & 127;
        sm[ww][ch] = g_s2[(size_t)ch * NVOX + base + ww];
    }
    __syncthreads();

    int L = seg[base + w];
    float r0=0,r1=0,r2=0,r3=0,r4=0,r5=0,r6=0,r7=0,r8=0,r9=0;
    if (L != 0) {
        int lb = (L - 1) * 6;
        // packed accumulators: A=(m0,m1d) B=(mdd,m1h) C=(mdh,mhh)
        //                      Dp=(m1w,mdw) E=(junk,mhw) F=(mww,junk)
        u64 A=0ull, B=0ull, C=0ull, Dp=0ull, E=0ull, F=0ull;
        int t0 = (w < RAD) ? RAD - w : 0;
        int t1 = (w > WW - 1 - RAD) ? (WW - 1 - w) + RAD : TAPS - 1;
        for (int t = t0; t <= t1; ++t) {
            int pos = w + t - RAD;
            float k0 = sw0[t];
            float dd = (float)(t - RAD);
            float k1 = k0 * dd;
            float k2 = k1 * dd;
            const float* row = &sm[pos][lb];
            u64 P01 = *(const u64*)(row + 0);
            u64 P23 = *(const u64*)(row + 2);
            u64 P45 = *(const u64*)(row + 4);
            u64 K0 = pk2(k0, k0), K1 = pk2(k1, k1), K2 = pk2(k2, k2);
            A  = ffma2(K0, P01, A);
            B  = ffma2(K0, P23, B);
            C  = ffma2(K0, P45, C);
            Dp = ffma2(K1, P01, Dp);
            E  = ffma2(K1, P23, E);   // .y accumulates k1*V3 = mhw
            F  = ffma2(K2, P01, F);   // .x accumulates k2*V0 = mww
        }
        float m0, m1d, mdd, m1h, mdh, mhh, m1w, mdw, junk, mhw, mww;
        upk2(m0, m1d, A); upk2(mdd, m1h, B); upk2(mdh, mhh, C);
        upk2(m1w, mdw, Dp); upk2(junk, mhw, E); upk2(mww, junk, F);

        float inv = 1.0f / m0;   // m0 >= w(0)^3 > 0 at a labeled voxel
        float od = m1d * inv, oh = m1h * inv, ow = m1w * inv;
        const float is2 = 1.0f / 25.0f;   // 1/sigma^2
        r0 = fmaf(od, 0.1f, 0.5f);        // (off/sigma)*0.5 + 0.5, sigma=5
        r1 = fmaf(oh, 0.1f, 0.5f);
        r2 = fmaf(ow, 0.1f, 0.5f);
        r3 = (mdd * inv - od * od) * is2;
        r4 = (mhh * inv - oh * oh) * is2;
        r5 = (mww * inv - ow * ow) * is2;
        r6 = (mdh * inv - od * oh) * is2;
        r7 = (mhw * inv - oh * ow) * is2;
        r8 = (mdw * inv - od * ow) * is2;
        r9 = m0;
    }
    float rr[10] = {r0,r1,r2,r3,r4,r5,r6,r7,r8,r9};
#pragma unroll
    for (int c = 0; c < 10; ++c) {
        float v = rr[c];
        v = fminf(fmaxf(v, 0.0f), 1.0f);
        out[(size_t)c * NVOX + base + w] = v;
    }
}

// ---------------------------------------------------------------------------
extern "C" void kernel_launch(void* const* d_in, const int* in_sizes, int n_in,
                              void* d_out, int out_size) {
    const int* seg = (const int*)d_in[0];
    // d_in[1] (coords) is a deterministic meshgrid == voxel indices; the
    // local-moment formulation makes it unnecessary.
    float* out = (float*)d_out;

    init_weights_kernel<<<1, 32>>>();
    pass1_kernel<<<dim3(HH, DD), 128>>>(seg);
    pass2_kernel<<<dim3(WW / 64, HH, DD / P2_DR), 256>>>();
    pass3_kernel<<<dim3(HH, DD), 128>>>(seg, out);
}

// round 3
// speedup vs baseline: 1.5870x; 1.5870x over previous
#include <cuda_runtime.h>
#include <cuda_fp16.h>
#include <math.h>

#define DD 128
#define HH 128
#define WW 128
#define HW (HH*WW)
#define NVOX (DD*HH*WW)
#define RAD 15
#define TAPS 31

// fp16 intermediates: pass1 out (8 labels x 3 h-orders), pass2 out (8 x 6 combos)
__device__ __half g_s1h[(size_t)24 * NVOX];   // ~100 MB
__device__ __half g_s2h[(size_t)48 * NVOX];   // ~201 MB
__device__ float  g_w0[TAPS];

// ---------------- f32x2 packed helpers ----------------
typedef unsigned long long u64;

__device__ __forceinline__ u64 pk2(float lo, float hi) {
    u64 r; asm("mov.b64 %0, {%1, %2};" : "=l"(r) : "f"(lo), "f"(hi)); return r;
}
__device__ __forceinline__ void upk2(float& lo, float& hi, u64 v) {
    asm("mov.b64 {%0, %1}, %2;" : "=f"(lo), "=f"(hi) : "l"(v));
}
__device__ __forceinline__ u64 ffma2(u64 a, u64 b, u64 c) {
    u64 r; asm("fma.rn.f32x2 %0, %1, %2, %3;" : "=l"(r) : "l"(a), "l"(b), "l"(c)); return r;
}

// ---------------------------------------------------------------------------
__global__ void init_weights_kernel() {
    int t = threadIdx.x;
    if (t >= TAPS) return;
    double s = 0.0;
    for (int i = 0; i < TAPS; ++i) {
        double dd = (double)(i - RAD) / 5.0;
        s += exp(-0.5 * dd * dd);
    }
    double d = (double)(t - RAD);
    g_w0[t] = (float)(exp(-0.5 * (d / 5.0) * (d / 5.0)) / s);
}

// ---------------------------------------------------------------------------
// Pass 1: blur along H. One-hot: per tap add (k0,k1,k2) to the matched label's
// private smem column. Rows 24..26 are a dummy sink for label 0.
// ---------------------------------------------------------------------------
__global__ __launch_bounds__(128) void pass1_kernel(const int* __restrict__ seg) {
    __shared__ float acc[27 * 128];
    __shared__ float sw0[TAPS];
    int w = threadIdx.x;
    int h = blockIdx.x;
    int d = blockIdx.y;
    if (w < TAPS) sw0[w] = g_w0[w];
#pragma unroll
    for (int i = 0; i < 27; ++i) acc[i * 128 + w] = 0.0f;
    __syncthreads();   // for sw0 only

    int lo = h - RAD; if (lo < 0) lo = 0;
    int hi = h + RAD; if (hi > HH - 1) hi = HH - 1;
    const int* p = seg + (size_t)d * HW + w;
    for (int hh = lo; hh <= hi; ++hh) {
        int s = __ldg(p + (size_t)hh * WW);
        int t = hh - h + RAD;
        float k0 = sw0[t];
        float dd = (float)(hh - h);
        float k1 = k0 * dd;
        float k2 = k1 * dd;
        int off = (s == 0) ? (24 * 128 + w) : ((s - 1) * 3 * 128 + w);
        acc[off]       += k0;
        acc[off + 128] += k1;
        acc[off + 256] += k2;
    }
    size_t idx = (size_t)d * HW + (size_t)h * WW + w;
#pragma unroll
    for (int c = 0; c < 24; ++c)
        g_s1h[(size_t)c * NVOX + idx] = __float2half(acc[c * 128 + w]);
}

// ---------------------------------------------------------------------------
// Pass 2: blur along D, f32x2 packed (thread = w-pair). Tile 32d x 64w.
// fp16 in (converted at staging), fp16 out (cvt.f16x2 at writeback).
// Combos: 0:(d0,h0) 1:(d1,h0) 2:(d2,h0) 3:(d0,h1) 4:(d1,h1) 5:(d0,h2)
// ---------------------------------------------------------------------------
#define P2_DR 32
#define P2_PP (P2_DR + 2*RAD)   // 62

__global__ __launch_bounds__(256) void pass2_kernel() {
    __shared__ __align__(16) float sb[3][P2_PP][64];   // 47616 B
    __shared__ float sw0[TAPS];
    int tid   = threadIdx.x;
    int wbase = blockIdx.x * 64;
    int h     = blockIdx.y;
    int dbase = blockIdx.z * P2_DR;
    if (tid < TAPS) sw0[tid] = g_w0[tid];
    int wi   = tid & 31;
    int grp  = tid >> 5;
    int dloc = grp * 4;

    for (int l = 0; l < 8; ++l) {
        __syncthreads();
        for (int c = 0; c < 3; ++c) {
            const __half* src = g_s1h + (size_t)(l * 3 + c) * NVOX + (size_t)h * WW + wbase;
            for (int i = tid; i < P2_PP * 32; i += 256) {
                int pp = i >> 5, pr = i & 31;      // pr indexes a w-pair
                int dd = dbase + pp - RAD;
                float2 v = make_float2(0.0f, 0.0f);
                if (dd >= 0 && dd < DD)
                    v = __half22float2(*(const __half2*)(src + (size_t)dd * HW + 2 * pr));
                sb[c][pp][2 * pr]     = v.x;
                sb[c][pp][2 * pr + 1] = v.y;
            }
        }
        __syncthreads();

        u64 acc[4][6];
#pragma unroll
        for (int o = 0; o < 4; ++o)
#pragma unroll
            for (int cc = 0; cc < 6; ++cc) acc[o][cc] = 0ull;

        u64 v0[4], v1[4], v2[4];
#pragma unroll
        for (int o = 0; o < 4; ++o) {
            v0[o] = *(const u64*)&sb[0][dloc + o][2 * wi];
            v1[o] = *(const u64*)&sb[1][dloc + o][2 * wi];
            v2[o] = *(const u64*)&sb[2][dloc + o][2 * wi];
        }
#pragma unroll
        for (int t = 0; t < TAPS; ++t) {
            float k0 = sw0[t];
            float dd = (float)(t - RAD);
            float k1 = k0 * dd;
            float k2 = k1 * dd;
            u64 K0 = pk2(k0, k0), K1 = pk2(k1, k1), K2 = pk2(k2, k2);
#pragma unroll
            for (int o = 0; o < 4; ++o) {
                acc[o][0] = ffma2(K0, v0[o], acc[o][0]);
                acc[o][1] = ffma2(K1, v0[o], acc[o][1]);
                acc[o][2] = ffma2(K2, v0[o], acc[o][2]);
                acc[o][3] = ffma2(K0, v1[o], acc[o][3]);
                acc[o][4] = ffma2(K1, v1[o], acc[o][4]);
                acc[o][5] = ffma2(K0, v2[o], acc[o][5]);
            }
            if (t < TAPS - 1) {
#pragma unroll
                for (int o = 0; o < 3; ++o) { v0[o] = v0[o+1]; v1[o] = v1[o+1]; v2[o] = v2[o+1]; }
                v0[3] = *(const u64*)&sb[0][dloc + t + 4][2 * wi];
                v1[3] = *(const u64*)&sb[1][dloc + t + 4][2 * wi];
                v2[3] = *(const u64*)&sb[2][dloc + t + 4][2 * wi];
            }
        }
        size_t obase = (size_t)(dbase + dloc) * HW + (size_t)h * WW + wbase + 2 * wi;
#pragma unroll
        for (int o = 0; o < 4; ++o)
#pragma unroll
            for (int cc = 0; cc < 6; ++cc) {
                float lo, hi; upk2(lo, hi, acc[o][cc]);
                *(__half2*)&g_s2h[(size_t)(l * 6 + cc) * NVOX + obase + (size_t)o * HW] =
                    __floats2half2_rn(lo, hi);
            }
    }
}

// ---------------------------------------------------------------------------
// Pass 3: blur along W + descriptor assembly, own-label only.
// smem voxel-major fp16, 8 halves per label (16B aligned): one LDS.128 per tap.
// Row pad 72 halves = 9 bank-quads -> conflict-free LDS.128 phases.
// ---------------------------------------------------------------------------
__global__ __launch_bounds__(128, 10) void pass3_kernel(const int* __restrict__ seg,
                                                        float* __restrict__ out) {
    __shared__ __align__(16) __half sm[WW][72];   // 18432 B
    __shared__ float sw0[TAPS];
    int w = threadIdx.x;
    int h = blockIdx.x;
    int d = blockIdx.y;
    if (w < TAPS) sw0[w] = g_w0[w];
    size_t base = (size_t)d * HW + (size_t)h * WW;
    for (int ch = 0; ch < 48; ++ch) {
        int l = ch / 6, c = ch - 6 * l;
        sm[w][l * 8 + c] = g_s2h[(size_t)ch * NVOX + base + w];
    }
    __syncthreads();

    int L = seg[base + w];
    float r0=0,r1=0,r2=0,r3=0,r4=0,r5=0,r6=0,r7=0,r8=0,r9=0;
    if (L != 0) {
        int lb8 = (L - 1) * 8;
        // packed accumulators: A=(m0,m1d) B=(mdd,m1h) C=(mdh,mhh)
        //                      Dp=(m1w,mdw) E=(junk,mhw) F=(mww,junk)
        u64 A=0ull, B=0ull, C=0ull, Dp=0ull, E=0ull, F=0ull;
        int t0 = (w < RAD) ? RAD - w : 0;
        int t1 = (w > WW - 1 - RAD) ? (WW - 1 - w) + RAD : TAPS - 1;
        for (int t = t0; t <= t1; ++t) {
            int pos = w + t - RAD;
            float k0 = sw0[t];
            float dd = (float)(t - RAD);
            float k1 = k0 * dd;
            float k2 = k1 * dd;
            uint4 pck = *(const uint4*)&sm[pos][lb8];     // 8 halves, 6 used
            float2 a01 = __half22float2(*(const __half2*)&pck.x);
            float2 a23 = __half22float2(*(const __half2*)&pck.y);
            float2 a45 = __half22float2(*(const __half2*)&pck.z);
            u64 P01 = pk2(a01.x, a01.y);
            u64 P23 = pk2(a23.x, a23.y);
            u64 P45 = pk2(a45.x, a45.y);
            u64 K0 = pk2(k0, k0), K1 = pk2(k1, k1), K2 = pk2(k2, k2);
            A  = ffma2(K0, P01, A);
            B  = ffma2(K0, P23, B);
            C  = ffma2(K0, P45, C);
            Dp = ffma2(K1, P01, Dp);
            E  = ffma2(K1, P23, E);   // .y accumulates k1*V3 = mhw
            F  = ffma2(K2, P01, F);   // .x accumulates k2*V0 = mww
        }
        float m0, m1d, mdd, m1h, mdh, mhh, m1w, mdw, junk, mhw, mww;
        upk2(m0, m1d, A); upk2(mdd, m1h, B); upk2(mdh, mhh, C);
        upk2(m1w, mdw, Dp); upk2(junk, mhw, E); upk2(mww, junk, F);

        float inv = 1.0f / m0;   // m0 >= w(0)^3 > 0 at a labeled voxel
        float od = m1d * inv, oh = m1h * inv, ow = m1w * inv;
        const float is2 = 1.0f / 25.0f;   // 1/sigma^2
        r0 = fmaf(od, 0.1f, 0.5f);        // (off/sigma)*0.5 + 0.5, sigma=5
        r1 = fmaf(oh, 0.1f, 0.5f);
        r2 = fmaf(ow, 0.1f, 0.5f);
        r3 = (mdd * inv - od * od) * is2;
        r4 = (mhh * inv - oh * oh) * is2;
        r5 = (mww * inv - ow * ow) * is2;
        r6 = (mdh * inv - od * oh) * is2;
        r7 = (mhw * inv - oh * ow) * is2;
        r8 = (mdw * inv - od * ow) * is2;
        r9 = m0;
    }
    float rr[10] = {r0,r1,r2,r3,r4,r5,r6,r7,r8,r9};
#pragma unroll
    for (int c = 0; c < 10; ++c) {
        float v = rr[c];
        v = fminf(fmaxf(v, 0.0f), 1.0f);
        out[(size_t)c * NVOX + base + w] = v;
    }
}

// ---------------------------------------------------------------------------
extern "C" void kernel_launch(void* const* d_in, const int* in_sizes, int n_in,
                              void* d_out, int out_size) {
    const int* seg = (const int*)d_in[0];
    // d_in[1] (coords) is a deterministic meshgrid == voxel indices; the
    // local-moment formulation makes it unnecessary.
    float* out = (float*)d_out;

    init_weights_kernel<<<1, 32>>>();
    pass1_kernel<<<dim3(HH, DD), 128>>>(seg);
    pass2_kernel<<<dim3(WW / 64, HH, DD / P2_DR), 256>>>();
    pass3_kernel<<<dim3(HH, DD), 128>>>(seg, out);
}